// round 2
// baseline (speedup 1.0000x reference)
#include <cuda_runtime.h>
#include <cuda_bf16.h>

// MultiHeadAttentionRelative: B=8192, J=81, DIM=128, HEADS=4, head_dim=32
// out[b,0,:] = concat_h( softmax_j( (Q.K + Q.Kr + Qr.K) * SCALE )_h @ V_h )
//
// HBM-bound: ~1.37 GB mandatory streaming of K/V/Q_r/K_r. Strategy: one CTA
// per batch row, 128 threads, float4 coalesced loads, all three score dots
// fused into one pass over K/K_r/Q_r, then softmax in smem, then one pass
// over V.

#define B_TOTAL 8192
#define J_LEN   81
#define DIM_    128
#define HEADS_  4
// SCALE = (DIM/HEADS)^-0.5 = 1/sqrt(32)
#define SCALE_F 0.17677669529663687f

__global__ void __launch_bounds__(128)
mhar_kernel(const float* __restrict__ Q,
            const float* __restrict__ K,
            const float* __restrict__ V,
            const float* __restrict__ Qr,
            const float* __restrict__ Kr,
            float* __restrict__ out)
{
    const int b    = blockIdx.x;
    const int t    = threadIdx.x;
    const int lane = t & 31;
    const int warp = t >> 5;
    const int h_of_lane = lane >> 3;   // head owning dims [4*lane, 4*lane+4)

    __shared__ float s_scores[HEADS_][J_LEN + 3];   // +3 pad
    __shared__ float s_acc[4][DIM_];                // per-warp partial outputs

    // Q row for this batch: lane holds dims [4*lane, 4*lane+4)
    const float4* q4p = reinterpret_cast<const float4*>(Q + (size_t)b * DIM_);
    const float4 q4 = q4p[lane];

    const size_t base = (size_t)b * J_LEN * DIM_;
    const float4* Kb  = reinterpret_cast<const float4*>(K  + base);
    const float4* Vb  = reinterpret_cast<const float4*>(V  + base);
    const float4* Qrb = reinterpret_cast<const float4*>(Qr + base);
    const float4* Krb = reinterpret_cast<const float4*>(Kr + base);

    // ---------------- Pass 1: scores (c_c + c_p + p_c) ----------------
    // warp w handles rows j = w, w+4, w+8, ...
    #pragma unroll 3
    for (int j = warp; j < J_LEN; j += 4) {
        const int idx = j * 32 + lane;
        const float4 k4  = Kb[idx];
        const float4 kr4 = Krb[idx];
        const float4 qr4 = Qrb[idx];

        // c_c: Q.K ; c_p: Q.Kr ; p_c: Qr.K  — fused per-element
        float s;
        s  = q4.x * k4.x;  s = fmaf(q4.y, k4.y, s);
        s  = fmaf(q4.z, k4.z, s);  s = fmaf(q4.w, k4.w, s);
        s  = fmaf(q4.x, kr4.x, s); s = fmaf(q4.y, kr4.y, s);
        s  = fmaf(q4.z, kr4.z, s); s = fmaf(q4.w, kr4.w, s);
        s  = fmaf(qr4.x, k4.x, s); s = fmaf(qr4.y, k4.y, s);
        s  = fmaf(qr4.z, k4.z, s); s = fmaf(qr4.w, k4.w, s);

        // reduce within each 8-lane group (one head = 8 lanes * 4 dims)
        s += __shfl_xor_sync(0xffffffffu, s, 1);
        s += __shfl_xor_sync(0xffffffffu, s, 2);
        s += __shfl_xor_sync(0xffffffffu, s, 4);

        if ((lane & 7) == 0)
            s_scores[h_of_lane][j] = s * SCALE_F;
    }
    __syncthreads();

    // ---------------- Softmax: warp w owns head w ----------------
    {
        const int h = warp;
        const bool a0 = (lane      < J_LEN);
        const bool a1 = (lane + 32 < J_LEN);
        const bool a2 = (lane + 64 < J_LEN);
        float v0 = a0 ? s_scores[h][lane]      : -1e30f;
        float v1 = a1 ? s_scores[h][lane + 32] : -1e30f;
        float v2 = a2 ? s_scores[h][lane + 64] : -1e30f;

        float m = fmaxf(v0, fmaxf(v1, v2));
        #pragma unroll
        for (int o = 16; o > 0; o >>= 1)
            m = fmaxf(m, __shfl_xor_sync(0xffffffffu, m, o));

        float e0 = a0 ? __expf(v0 - m) : 0.f;
        float e1 = a1 ? __expf(v1 - m) : 0.f;
        float e2 = a2 ? __expf(v2 - m) : 0.f;
        float ssum = e0 + e1 + e2;
        #pragma unroll
        for (int o = 16; o > 0; o >>= 1)
            ssum += __shfl_xor_sync(0xffffffffu, ssum, o);
        const float inv = __frcp_rn(ssum);

        if (a0) s_scores[h][lane]      = e0 * inv;
        if (a1) s_scores[h][lane + 32] = e1 * inv;
        if (a2) s_scores[h][lane + 64] = e2 * inv;
    }
    __syncthreads();

    // ---------------- Pass 2: weighted V accumulation ----------------
    float4 acc = make_float4(0.f, 0.f, 0.f, 0.f);
    #pragma unroll 3
    for (int j = warp; j < J_LEN; j += 4) {
        const float  p  = s_scores[h_of_lane][j];   // broadcast within 8-lane group
        const float4 v4 = Vb[j * 32 + lane];
        acc.x = fmaf(p, v4.x, acc.x);
        acc.y = fmaf(p, v4.y, acc.y);
        acc.z = fmaf(p, v4.z, acc.z);
        acc.w = fmaf(p, v4.w, acc.w);
    }

    // combine partials across the 4 warps
    reinterpret_cast<float4*>(s_acc[warp])[lane] = acc;
    __syncthreads();

    if (warp == 0) {
        const float4 a0 = reinterpret_cast<const float4*>(s_acc[0])[lane];
        const float4 a1 = reinterpret_cast<const float4*>(s_acc[1])[lane];
        const float4 a2 = reinterpret_cast<const float4*>(s_acc[2])[lane];
        const float4 a3 = reinterpret_cast<const float4*>(s_acc[3])[lane];
        float4 r;
        r.x = (a0.x + a1.x) + (a2.x + a3.x);
        r.y = (a0.y + a1.y) + (a2.y + a3.y);
        r.z = (a0.z + a1.z) + (a2.z + a3.z);
        r.w = (a0.w + a1.w) + (a2.w + a3.w);
        reinterpret_cast<float4*>(out + (size_t)b * DIM_)[lane] = r;
    }
}

extern "C" void kernel_launch(void* const* d_in, const int* in_sizes, int n_in,
                              void* d_out, int out_size)
{
    const float* Q  = (const float*)d_in[0];
    const float* K  = (const float*)d_in[1];
    const float* V  = (const float*)d_in[2];
    const float* Qr = (const float*)d_in[3];
    const float* Kr = (const float*)d_in[4];
    float* out = (float*)d_out;

    mhar_kernel<<<B_TOTAL, 128>>>(Q, K, V, Qr, Kr, out);
}

// round 3
// speedup vs baseline: 1.0327x; 1.0327x over previous
#include <cuda_runtime.h>
#include <cuda_bf16.h>

// MultiHeadAttentionRelative: B=8192, J=81, DIM=128, HEADS=4, head_dim=32
// out[b,0,:] = concat_h( softmax_j( (Q.K + Q.Kr + Qr.K) * SCALE )_h @ V_h )
//
// HBM-bound (~1.37 GB mandatory stream). R2: single-pass online softmax —
// K/Kr/Qr/V all loaded in ONE streaming loop (4x LDG.128 per iter, max MLP,
// no barrier on the memory path). Per-8-lane-group flash-style running
// (m, sum, acc); tiny cross-warp combine at the end.

#define B_TOTAL 8192
#define J_LEN   81
#define DIM_    128
#define HEADS_  4
// SCALE = (DIM/HEADS)^-0.5 = 1/sqrt(32)
#define SCALE_F 0.17677669529663687f

__global__ void __launch_bounds__(128)
mhar_kernel(const float* __restrict__ Q,
            const float* __restrict__ K,
            const float* __restrict__ V,
            const float* __restrict__ Qr,
            const float* __restrict__ Kr,
            float* __restrict__ out)
{
    const int b    = blockIdx.x;
    const int t    = threadIdx.x;
    const int lane = t & 31;
    const int warp = t >> 5;
    const int h    = lane >> 3;   // head owning dims [4*lane, 4*lane+4)

    __shared__ float s_m  [4][HEADS_];
    __shared__ float s_sum[4][HEADS_];
    __shared__ float s_acc[4][DIM_];

    // Q row: lane holds dims [4*lane, 4*lane+4)
    const float4 q4 = reinterpret_cast<const float4*>(Q + (size_t)b * DIM_)[lane];

    const size_t base = (size_t)b * J_LEN * DIM_;
    const float4* Kb  = reinterpret_cast<const float4*>(K  + base);
    const float4* Vb  = reinterpret_cast<const float4*>(V  + base);
    const float4* Qrb = reinterpret_cast<const float4*>(Qr + base);
    const float4* Krb = reinterpret_cast<const float4*>(Kr + base);

    // ---- single streaming pass: score + online softmax + V accumulate ----
    float  m_run = -1e30f;
    float  s_run = 0.f;
    float4 acc   = make_float4(0.f, 0.f, 0.f, 0.f);

    // warp w handles rows j = w, w+4, w+8, ...
    #pragma unroll 3
    for (int j = warp; j < J_LEN; j += 4) {
        const int idx = j * 32 + lane;
        const float4 k4  = Kb[idx];
        const float4 kr4 = Krb[idx];
        const float4 qr4 = Qrb[idx];
        const float4 v4  = Vb[idx];

        // fused c_c + c_p + p_c partial dot (this lane's 4 dims)
        float s;
        s  = q4.x * k4.x;          s = fmaf(q4.y,  k4.y,  s);
        s  = fmaf(q4.z,  k4.z,  s); s = fmaf(q4.w,  k4.w,  s);
        s  = fmaf(q4.x,  kr4.x, s); s = fmaf(q4.y,  kr4.y, s);
        s  = fmaf(q4.z,  kr4.z, s); s = fmaf(q4.w,  kr4.w, s);
        s  = fmaf(qr4.x, k4.x,  s); s = fmaf(qr4.y, k4.y,  s);
        s  = fmaf(qr4.z, k4.z,  s); s = fmaf(qr4.w, k4.w,  s);

        // butterfly-reduce within the 8-lane head group (all lanes get sum)
        s += __shfl_xor_sync(0xffffffffu, s, 1);
        s += __shfl_xor_sync(0xffffffffu, s, 2);
        s += __shfl_xor_sync(0xffffffffu, s, 4);
        s *= SCALE_F;

        // online softmax update (identical across the 8 lanes of a group)
        const float m_new  = fmaxf(m_run, s);
        const float factor = __expf(m_run - m_new);
        const float p      = __expf(s - m_new);
        s_run = fmaf(s_run, factor, p);
        m_run = m_new;
        acc.x = fmaf(acc.x, factor, p * v4.x);
        acc.y = fmaf(acc.y, factor, p * v4.y);
        acc.z = fmaf(acc.z, factor, p * v4.z);
        acc.w = fmaf(acc.w, factor, p * v4.w);
    }

    // ---- publish per-warp partials ----
    if ((lane & 7) == 0) {
        s_m  [warp][h] = m_run;
        s_sum[warp][h] = s_run;
    }
    reinterpret_cast<float4*>(s_acc[warp])[lane] = acc;
    __syncthreads();

    // ---- warp 0 combines the 4 warps' (m, sum, acc) per head ----
    if (warp == 0) {
        const float m0 = s_m[0][h], m1 = s_m[1][h], m2 = s_m[2][h], m3 = s_m[3][h];
        const float M  = fmaxf(fmaxf(m0, m1), fmaxf(m2, m3));
        const float f0 = __expf(m0 - M);
        const float f1 = __expf(m1 - M);
        const float f2 = __expf(m2 - M);
        const float f3 = __expf(m3 - M);

        const float T = s_sum[0][h] * f0 + s_sum[1][h] * f1
                      + s_sum[2][h] * f2 + s_sum[3][h] * f3;
        const float inv = __frcp_rn(T);

        const float4 a0 = reinterpret_cast<const float4*>(s_acc[0])[lane];
        const float4 a1 = reinterpret_cast<const float4*>(s_acc[1])[lane];
        const float4 a2 = reinterpret_cast<const float4*>(s_acc[2])[lane];
        const float4 a3 = reinterpret_cast<const float4*>(s_acc[3])[lane];

        float4 r;
        r.x = ((a0.x * f0 + a1.x * f1) + (a2.x * f2 + a3.x * f3)) * inv;
        r.y = ((a0.y * f0 + a1.y * f1) + (a2.y * f2 + a3.y * f3)) * inv;
        r.z = ((a0.z * f0 + a1.z * f1) + (a2.z * f2 + a3.z * f3)) * inv;
        r.w = ((a0.w * f0 + a1.w * f1) + (a2.w * f2 + a3.w * f3)) * inv;
        reinterpret_cast<float4*>(out + (size_t)b * DIM_)[lane] = r;
    }
}

extern "C" void kernel_launch(void* const* d_in, const int* in_sizes, int n_in,
                              void* d_out, int out_size)
{
    const float* Q  = (const float*)d_in[0];
    const float* K  = (const float*)d_in[1];
    const float* V  = (const float*)d_in[2];
    const float* Qr = (const float*)d_in[3];
    const float* Kr = (const float*)d_in[4];
    float* out = (float*)d_out;

    mhar_kernel<<<B_TOTAL, 128>>>(Q, K, V, Qr, Kr, out);
}